// round 13
// baseline (speedup 1.0000x reference)
#include <cuda_runtime.h>
#include <cuda_fp16.h>

#define BATCH   64
#define NATOMS  64
#define HDIM    256
#define H2      (HDIM / 2)             /* 128 half2 per row */
#define NPH     4                      /* graph phases of 16 */

/* s = [h1@W1[:H]+b1 ; h2@W1[H:]] packed half2 (4 MB) */
__device__ unsigned g_sh[2 * BATCH * NATOMS * H2];
__device__ float g_rp[BATCH * NATOMS * 2];    /* row partials [g][i][jh]        */
__device__ float g_cp[BATCH * 2 * 32 * 4];    /* col partials [g][jh][jl][ihq]  */

__device__ __forceinline__ unsigned pack_h2(float x, float y) {
    __half2 h = __floats2half2_rn(x, y);
    return *reinterpret_cast<unsigned*>(&h);
}
__device__ __forceinline__ unsigned tanh2u(unsigned x) {
    unsigned y; asm("tanh.approx.f16x2 %0, %1;" : "=r"(y) : "r"(x)); return y;
}
__device__ __forceinline__ __half2 u2h(unsigned u) {
    return *reinterpret_cast<__half2*>(&u);
}
__device__ __forceinline__ unsigned hadd2u(unsigned a, unsigned b) {
    __half2 r = __hadd2(u2h(a), u2h(b));
    return *reinterpret_cast<unsigned*>(&r);
}
__device__ __forceinline__ void cp_async16(void* smem, const void* gmem) {
    unsigned s = (unsigned)__cvta_generic_to_shared(smem);
    asm volatile("cp.async.cg.shared.global [%0], [%1], 16;" :: "r"(s), "l"(gmem));
}

/* ===== tf32 tensor GEMM, proven body, one 16-graph phase per launch ===== */
__global__ void __launch_bounds__(128) gemm_phase(
    const float* __restrict__ h1, const float* __restrict__ h2,
    const float* __restrict__ W1, const float* __restrict__ b1, int p)
{
    __shared__ float As[2][64 * 36];   /* [row][k], pad 36 -> conflict-free */
    __shared__ float Bs[2][32 * 72];   /* [k][n],   pad 72 -> conflict-free */

    const int rb = blockIdx.x;                 /* 0..31 row-blocks this phase */
    const int n0 = blockIdx.y * 64;
    const bool second = (rb >= 16);
    const int row_local = p * 1024 + (rb & 15) * 64;   /* row in h1/h2 */
    const int row0 = (second ? BATCH * NATOMS : 0) + row_local;
    const float* A = (second ? h2 : h1) + (size_t)row_local * HDIM;
    const float* W = W1 + (second ? HDIM * HDIM : 0);

    const int tid = threadIdx.x;
    const int lane = tid & 31, w = tid >> 5;
    const int wm = w >> 1, wn = w & 1;
    const int gid = lane >> 2, tig = lane & 3;

    int ar[4], ac[4], bk[4], bn[4];
#pragma unroll
    for (int l = 0; l < 4; l++) {
        int f = tid + l * 128;
        ar[l] = f >> 3;  ac[l] = f & 7;
        bk[l] = f >> 4;  bn[l] = f & 15;
    }

    float acc[2][4][4];
#pragma unroll
    for (int mt = 0; mt < 2; mt++)
#pragma unroll
        for (int nt = 0; nt < 4; nt++)
#pragma unroll
            for (int q = 0; q < 4; q++) acc[mt][nt][q] = 0.f;

#pragma unroll
    for (int l = 0; l < 4; l++)
        cp_async16(&As[0][ar[l] * 36 + ac[l] * 4], A + ar[l] * HDIM + ac[l] * 4);
#pragma unroll
    for (int l = 0; l < 4; l++)
        cp_async16(&Bs[0][bk[l] * 72 + bn[l] * 4], W + bk[l] * HDIM + n0 + bn[l] * 4);
    asm volatile("cp.async.commit_group;");

    for (int kci = 0; kci < 8; kci++) {
        const int s = kci & 1;
        if (kci + 1 < 8) {
            const int kc = (kci + 1) * 32;
#pragma unroll
            for (int l = 0; l < 4; l++)
                cp_async16(&As[s ^ 1][ar[l] * 36 + ac[l] * 4],
                           A + ar[l] * HDIM + kc + ac[l] * 4);
#pragma unroll
            for (int l = 0; l < 4; l++)
                cp_async16(&Bs[s ^ 1][bk[l] * 72 + bn[l] * 4],
                           W + (kc + bk[l]) * HDIM + n0 + bn[l] * 4);
            asm volatile("cp.async.commit_group;");
            asm volatile("cp.async.wait_group 1;");
        } else {
            asm volatile("cp.async.wait_group 0;");
        }
        __syncthreads();

        const unsigned* Au = (const unsigned*)As[s];
        const unsigned* Bu = (const unsigned*)Bs[s];
#pragma unroll
        for (int ks = 0; ks < 4; ks++) {
            unsigned a[2][4], bfr[4][2];
#pragma unroll
            for (int mt = 0; mt < 2; mt++) {
                int r = wm * 32 + mt * 16 + gid;
                int kk = ks * 8 + tig;
                a[mt][0] = Au[r * 36 + kk];
                a[mt][1] = Au[(r + 8) * 36 + kk];
                a[mt][2] = Au[r * 36 + kk + 4];
                a[mt][3] = Au[(r + 8) * 36 + kk + 4];
            }
#pragma unroll
            for (int nt = 0; nt < 4; nt++) {
                int c = wn * 32 + nt * 8 + gid;
                bfr[nt][0] = Bu[(ks * 8 + tig) * 72 + c];
                bfr[nt][1] = Bu[(ks * 8 + tig + 4) * 72 + c];
            }
#pragma unroll
            for (int mt = 0; mt < 2; mt++)
#pragma unroll
                for (int nt = 0; nt < 4; nt++)
                    asm volatile(
                        "mma.sync.aligned.m16n8k8.row.col.f32.tf32.tf32.f32 "
                        "{%0,%1,%2,%3}, {%4,%5,%6,%7}, {%8,%9}, {%0,%1,%2,%3};"
                        : "+f"(acc[mt][nt][0]), "+f"(acc[mt][nt][1]),
                          "+f"(acc[mt][nt][2]), "+f"(acc[mt][nt][3])
                        : "r"(a[mt][0]), "r"(a[mt][1]), "r"(a[mt][2]), "r"(a[mt][3]),
                          "r"(bfr[nt][0]), "r"(bfr[nt][1]));
        }
        __syncthreads();
    }

#pragma unroll
    for (int mt = 0; mt < 2; mt++) {
        int r = row0 + wm * 32 + mt * 16 + gid;
#pragma unroll
        for (int nt = 0; nt < 4; nt++) {
            int col = n0 + wn * 32 + nt * 8 + tig * 2;
            float bx = 0.f, by = 0.f;
            if (!second) { float2 bv = *(const float2*)(b1 + col); bx = bv.x; by = bv.y; }
            g_sh[r * H2 + (col >> 1)]       = pack_h2(acc[mt][nt][0] + bx, acc[mt][nt][1] + by);
            g_sh[(r + 8) * H2 + (col >> 1)] = pack_h2(acc[mt][nt][2] + bx, acc[mt][nt][3] + by);
        }
    }
}

/* ===== score phase: 128 CTAs (16g x 2jh x 4ihq) x 512 thr, proven loop ===== */
__global__ void __launch_bounds__(512) score_phase(const float* __restrict__ W2, int p)
{
    __shared__ unsigned s1s[16 * 128];   /* [i][hh] half2, this quarter    */
    __shared__ unsigned s2s[32 * 129];   /* [j][hh] pad 129: conflict-free */
    __shared__ float2   w2s[128];
    __shared__ float    colbuf[16][32];

    const int jh = blockIdx.x, ihq = blockIdx.y, g = p * 16 + blockIdx.z;
    const int tid = threadIdx.x, lane = tid & 31, w = tid >> 5;

    if (tid < 128) w2s[tid] = *(const float2*)(W2 + tid * 2);

    /* s1: 16 rows x 128 half2 = 512 uint4 (1/thread), linear */
    const unsigned* s1g = g_sh + (size_t)(g * NATOMS + ihq * 16) * H2;
    *(uint4*)&s1s[tid * 4] = *(const uint4*)(s1g + tid * 4);

    /* s2: 32 rows, pad-129 scalar stores (2 uint4/thread) — proven pattern */
    const unsigned* s2g = g_sh + (size_t)(BATCH * NATOMS + g * NATOMS + jh * 32) * H2;
#pragma unroll
    for (int l = 0; l < 2; l++) {
        int f = tid + l * 512;
        int j = f >> 5, q = f & 31;
        uint4 v = *(const uint4*)(s2g + f * 4);
        unsigned* d = &s2s[j * 129 + q * 4];
        d[0] = v.x; d[1] = v.y; d[2] = v.z; d[3] = v.w;
    }
    __syncthreads();

    /* warp w owns i row w (of this 16-row quarter); lane = local j */
    const unsigned* s2row = &s2s[lane * 129];
    const unsigned* s1w = &s1s[w * 128];
    float accA = 0.f, accB = 0.f;

#pragma unroll 4
    for (int hh = 0; hh < 128; hh++) {
        float2 wv = w2s[hh];           /* broadcast */
        unsigned b2 = s2row[hh];       /* conflict-free */
        unsigned a2 = s1w[hh];         /* broadcast */
        unsigned th = tanh2u(hadd2u(a2, b2));
        float2 tf = __half22float2(u2h(th));
        accA = fmaf(wv.x, tf.x, accA);
        accB = fmaf(wv.y, tf.y, accB);
    }

    float e = __expf(accA + accB);     /* bounded scores: no max pass */
    float rs = e;
#pragma unroll
    for (int o = 16; o > 0; o >>= 1)
        rs += __shfl_xor_sync(0xffffffffu, rs, o);
    if (lane == 0)
        g_rp[(g * NATOMS + ihq * 16 + w) * 2 + jh] = rs;

    colbuf[w][lane] = e;               /* one i-row per warp */
    __syncthreads();
    if (tid < 32) {
        float s = 0.f;
#pragma unroll
        for (int ww = 0; ww < 16; ww++) s += colbuf[ww][tid];
        g_cp[((g * 2 + jh) * 32 + tid) * 4 + ihq] = s;
    }
}

/* ---------------- normalize ---------------- */
__global__ void __launch_bounds__(64) finalize_kernel(float* __restrict__ out)
{
    int b = blockIdx.x, i = threadIdx.x;
    float r = g_rp[(b * 64 + i) * 2] + g_rp[(b * 64 + i) * 2 + 1];
    int jjh = i >> 5, jl = i & 31;
    const float* cp = &g_cp[((b * 2 + jjh) * 32 + jl) * 4];
    float c = (cp[0] + cp[1]) + (cp[2] + cp[3]);
    __shared__ float red[64];
    red[i] = r;
    __syncthreads();
    if (i < 32) {
        float v = red[i] + red[i + 32];
#pragma unroll
        for (int o = 16; o > 0; o >>= 1)
            v += __shfl_xor_sync(0xffffffffu, v, o);
        if (i == 0) red[0] = v;
    }
    __syncthreads();
    float inv = 1.f / red[0];
    out[b * 64 + i] = r * inv;
    out[BATCH * NATOMS + b * 64 + i] = c * inv;
}

/* side stream + events, created once at load (handles only, no device mem) */
static cudaStream_t g_s2 = nullptr;
static cudaEvent_t  g_evG[NPH], g_evS = nullptr;
namespace {
struct HxInit {
    HxInit() {
        bool ok = (cudaStreamCreateWithFlags(&g_s2, cudaStreamNonBlocking) == cudaSuccess);
        for (int p = 0; p < NPH && ok; p++)
            ok = (cudaEventCreateWithFlags(&g_evG[p], cudaEventDisableTiming) == cudaSuccess);
        if (ok) ok = (cudaEventCreateWithFlags(&g_evS, cudaEventDisableTiming) == cudaSuccess);
        if (!ok) g_s2 = nullptr;
    }
} g_hx_init;
}

extern "C" void kernel_launch(void* const* d_in, const int* in_sizes, int n_in,
                              void* d_out, int out_size)
{
    const float *h1 = nullptr, *h2 = nullptr, *W1 = nullptr,
                *b1 = nullptr, *W2 = nullptr;
    for (int idx = 0; idx < n_in; idx++) {
        int sz = in_sizes[idx];
        if (sz == BATCH * NATOMS * HDIM) {
            if (!h1) h1 = (const float*)d_in[idx];
            else if (!h2) h2 = (const float*)d_in[idx];
        } else if (sz == 2 * HDIM * HDIM) {
            W1 = (const float*)d_in[idx];
        } else if (sz == HDIM) {
            if (!b1) b1 = (const float*)d_in[idx];
            else if (!W2) W2 = (const float*)d_in[idx];
        }
    }
    float* out = (float*)d_out;

    if (g_s2) {
        /* pipelined: G0 -> (S0 || G1) -> (S1 || G2) -> (S2 || G3) -> S3 -> F */
        for (int p = 0; p < NPH; p++) {
            gemm_phase<<<dim3(32, 4), 128>>>(h1, h2, W1, b1, p);
            cudaEventRecord(g_evG[p], 0);
        }
        for (int p = 0; p < NPH; p++) {
            cudaStreamWaitEvent(g_s2, g_evG[p], 0);
            score_phase<<<dim3(2, 4, 16), 512, 0, g_s2>>>(W2, p);
        }
        cudaEventRecord(g_evS, g_s2);
        cudaStreamWaitEvent(0, g_evS, 0);
        finalize_kernel<<<BATCH, 64>>>(out);
    } else {
        /* sequential fallback: identical work */
        for (int p = 0; p < NPH; p++)
            gemm_phase<<<dim3(32, 4), 128>>>(h1, h2, W1, b1, p);
        for (int p = 0; p < NPH; p++)
            score_phase<<<dim3(2, 4, 16), 512>>>(W2, p);
        finalize_kernel<<<BATCH, 64>>>(out);
    }
}

// round 14
// speedup vs baseline: 1.0307x; 1.0307x over previous
#include <cuda_runtime.h>
#include <cuda_fp16.h>

#define BATCH   64
#define NATOMS  64
#define HDIM    256
#define NROWS   (2 * BATCH * NATOMS)   /* 8192 */
#define H2      (HDIM / 2)             /* 128 half2 per row */
#define SMEM_BYTES 36864

/* s = [h1@W1[:H]+b1 ; h2@W1[H:]] packed half2 (4 MB) */
__device__ unsigned g_sh[NROWS * H2];
__device__ float g_rp[BATCH * NATOMS * 2];   /* row partials, 2 jh-halves */
__device__ float g_cp[BATCH * NATOMS * 2];   /* col partials, 2 ih-halves */
__device__ int   g_cnt[BATCH];               /* GEMM arrivals (target 8)  */
__device__ int   g_done[BATCH];              /* score consumers (4)       */

__device__ __forceinline__ unsigned pack_h2(float x, float y) {
    __half2 h = __floats2half2_rn(x, y);
    return *reinterpret_cast<unsigned*>(&h);
}
__device__ __forceinline__ unsigned tanh2u(unsigned x) {
    unsigned y; asm("tanh.approx.f16x2 %0, %1;" : "=r"(y) : "r"(x)); return y;
}
__device__ __forceinline__ __half2 u2h(unsigned u) {
    return *reinterpret_cast<__half2*>(&u);
}
__device__ __forceinline__ unsigned hadd2u(unsigned a, unsigned b) {
    __half2 r = __hadd2(u2h(a), u2h(b));
    return *reinterpret_cast<unsigned*>(&r);
}
__device__ __forceinline__ void cp_async16(void* smem, const void* gmem) {
    unsigned s = (unsigned)__cvta_generic_to_shared(smem);
    asm volatile("cp.async.cg.shared.global [%0], [%1], 16;" :: "r"(s), "l"(gmem));
}
__device__ __forceinline__ int ldvol(const int* p) {
    int v; asm volatile("ld.volatile.global.b32 %0, [%1];" : "=r"(v) : "l"(p)); return v;
}

/* ============ merged kernel: CTAs 0-511 GEMM, 512-767 score ============ */
__global__ void __launch_bounds__(256) merged_kernel(
    const float* __restrict__ h1, const float* __restrict__ h2,
    const float* __restrict__ W1, const float* __restrict__ b1,
    const float* __restrict__ W2)
{
    extern __shared__ char sm[];
    const int cta = blockIdx.x;
    const int tid = threadIdx.x, lane = tid & 31, w = tid >> 5;

    if (cta < 512) {
        /* ---------------- GEMM role (R4-proven 256-thr body) ---------------- */
        float* AsB = (float*)sm;                 /* [2][64*36] = 4608 floats */
        float* BsB = AsB + 4608;                 /* [2][32*72] = 4608 floats */

        const int rb = cta >> 2;                 /* row-block 0..127 */
        const int n0 = (cta & 3) * 64;
        const bool second = (rb >= 64);
        const int graph = second ? rb - 64 : rb;
        const int row0 = rb * 64;
        const float* A = (second ? h2 : h1) + (size_t)(graph * NATOMS) * HDIM * 1
                         + (size_t)0;            /* rows 64*graph.. */
        const float* Ap = (second ? h2 : h1) + (size_t)(row0 - (second ? BATCH * NATOMS : 0)) * HDIM;
        const float* W = W1 + (second ? HDIM * HDIM : 0);
        (void)A;

        const int wm = w >> 2, wn = w & 3;       /* 2x4 warp grid: m32 x n16 */
        const int gid = lane >> 2, tig = lane & 3;

        int ar[2], ac[2], bk[2], bn[2];
#pragma unroll
        for (int l = 0; l < 2; l++) {
            int f = tid + l * 256;
            ar[l] = f >> 3;  ac[l] = f & 7;
            bk[l] = f >> 4;  bn[l] = f & 15;
        }

        float acc[2][2][4];
#pragma unroll
        for (int mt = 0; mt < 2; mt++)
#pragma unroll
            for (int nt = 0; nt < 2; nt++)
#pragma unroll
                for (int q = 0; q < 4; q++) acc[mt][nt][q] = 0.f;

#pragma unroll
        for (int l = 0; l < 2; l++)
            cp_async16(&AsB[ar[l] * 36 + ac[l] * 4], Ap + ar[l] * HDIM + ac[l] * 4);
#pragma unroll
        for (int l = 0; l < 2; l++)
            cp_async16(&BsB[bk[l] * 72 + bn[l] * 4], W + bk[l] * HDIM + n0 + bn[l] * 4);
        asm volatile("cp.async.commit_group;");

        for (int kci = 0; kci < 8; kci++) {
            const int s = kci & 1;
            if (kci + 1 < 8) {
                const int kc = (kci + 1) * 32;
                const int so = s ^ 1;
#pragma unroll
                for (int l = 0; l < 2; l++)
                    cp_async16(&AsB[so * 2304 + ar[l] * 36 + ac[l] * 4],
                               Ap + ar[l] * HDIM + kc + ac[l] * 4);
#pragma unroll
                for (int l = 0; l < 2; l++)
                    cp_async16(&BsB[so * 2304 + bk[l] * 72 + bn[l] * 4],
                               W + (kc + bk[l]) * HDIM + n0 + bn[l] * 4);
                asm volatile("cp.async.commit_group;");
                asm volatile("cp.async.wait_group 1;");
            } else {
                asm volatile("cp.async.wait_group 0;");
            }
            __syncthreads();

            const unsigned* Au = (const unsigned*)(AsB + s * 2304);
            const unsigned* Bu = (const unsigned*)(BsB + s * 2304);
#pragma unroll
            for (int ks = 0; ks < 4; ks++) {
                unsigned a[2][4], bfr[2][2];
#pragma unroll
                for (int mt = 0; mt < 2; mt++) {
                    int r = wm * 32 + mt * 16 + gid;
                    int kk = ks * 8 + tig;
                    a[mt][0] = Au[r * 36 + kk];
                    a[mt][1] = Au[(r + 8) * 36 + kk];
                    a[mt][2] = Au[r * 36 + kk + 4];
                    a[mt][3] = Au[(r + 8) * 36 + kk + 4];
                }
#pragma unroll
                for (int nt = 0; nt < 2; nt++) {
                    int c = wn * 16 + nt * 8 + gid;
                    bfr[nt][0] = Bu[(ks * 8 + tig) * 72 + c];
                    bfr[nt][1] = Bu[(ks * 8 + tig + 4) * 72 + c];
                }
#pragma unroll
                for (int mt = 0; mt < 2; mt++)
#pragma unroll
                    for (int nt = 0; nt < 2; nt++)
                        asm volatile(
                            "mma.sync.aligned.m16n8k8.row.col.f32.tf32.tf32.f32 "
                            "{%0,%1,%2,%3}, {%4,%5,%6,%7}, {%8,%9}, {%0,%1,%2,%3};"
                            : "+f"(acc[mt][nt][0]), "+f"(acc[mt][nt][1]),
                              "+f"(acc[mt][nt][2]), "+f"(acc[mt][nt][3])
                            : "r"(a[mt][0]), "r"(a[mt][1]), "r"(a[mt][2]), "r"(a[mt][3]),
                              "r"(bfr[nt][0]), "r"(bfr[nt][1]));
            }
            __syncthreads();
        }

#pragma unroll
        for (int mt = 0; mt < 2; mt++) {
            int r = row0 + wm * 32 + mt * 16 + gid;
#pragma unroll
            for (int nt = 0; nt < 2; nt++) {
                int col = n0 + wn * 16 + nt * 8 + tig * 2;
                float bx = 0.f, by = 0.f;
                if (!second) { float2 bv = *(const float2*)(b1 + col); bx = bv.x; by = bv.y; }
                g_sh[r * H2 + (col >> 1)]       = pack_h2(acc[mt][nt][0] + bx, acc[mt][nt][1] + by);
                g_sh[(r + 8) * H2 + (col >> 1)] = pack_h2(acc[mt][nt][2] + bx, acc[mt][nt][3] + by);
            }
        }

        /* signal: this graph-chunk is done (8 CTAs per graph) */
        __threadfence();
        __syncthreads();
        if (tid == 0) atomicAdd(&g_cnt[graph], 1);

    } else {
        /* ---------------- score role (R2-proven body) ---------------- */
        unsigned* s1s = (unsigned*)sm;                 /* 32*128 = 4096  */
        unsigned* s2s = s1s + 4096;                    /* 32*129 = 4128  */
        float2*   w2s = (float2*)(s2s + 4128);         /* 128            */
        float*    colbuf = (float*)(w2s + 128);        /* [8][32]        */

        const int sb = cta - 512;
        const int g = sb >> 2, jh = (sb >> 1) & 1, ih = sb & 1;

        if (tid < 128) w2s[tid] = *(const float2*)(W2 + tid * 2);

        /* wait for this graph's 8 GEMM CTAs */
        if (tid == 0) {
            while (ldvol(&g_cnt[g]) < 8) __nanosleep(64);
        }
        __syncthreads();
        __threadfence();

        const unsigned* s1g = g_sh + (size_t)(g * NATOMS + ih * 32) * H2;
#pragma unroll
        for (int l = 0; l < 4; l++) {
            int f = tid + l * 256;
            *(uint4*)&s1s[f * 4] = *(const uint4*)(s1g + f * 4);
        }
        const unsigned* s2g = g_sh + (size_t)(BATCH * NATOMS + g * NATOMS + jh * 32) * H2;
#pragma unroll
        for (int l = 0; l < 4; l++) {
            int f = tid + l * 256;
            int j = f >> 5, q = f & 31;
            uint4 v = *(const uint4*)(s2g + f * 4);
            unsigned* d = &s2s[j * 129 + q * 4];
            d[0] = v.x; d[1] = v.y; d[2] = v.z; d[3] = v.w;
        }
        __syncthreads();

        const unsigned* s2row = &s2s[lane * 129];
        float accA[4], accB[4];
#pragma unroll
        for (int ii = 0; ii < 4; ii++) { accA[ii] = 0.f; accB[ii] = 0.f; }

#pragma unroll 4
        for (int hh = 0; hh < 128; hh++) {
            float2 wv = w2s[hh];           /* broadcast */
            unsigned b2 = s2row[hh];       /* conflict-free */
#pragma unroll
            for (int ii = 0; ii < 4; ii++) {
                unsigned a2 = s1s[(w * 4 + ii) * 128 + hh];   /* broadcast */
                unsigned th = tanh2u(hadd2u(a2, b2));
                float2 tf = __half22float2(u2h(th));
                accA[ii] = fmaf(wv.x, tf.x, accA[ii]);
                accB[ii] = fmaf(wv.y, tf.y, accB[ii]);
            }
        }

        float colacc = 0.f;
#pragma unroll
        for (int ii = 0; ii < 4; ii++) {
            float e = __expf(accA[ii] + accB[ii]);   /* bounded: no max pass */
            colacc += e;
            float rs = e;
#pragma unroll
            for (int o = 16; o > 0; o >>= 1)
                rs += __shfl_xor_sync(0xffffffffu, rs, o);
            if (lane == 0)
                g_rp[(g * NATOMS + ih * 32 + w * 4 + ii) * 2 + jh] = rs;
        }
        colbuf[w * 32 + lane] = colacc;
        __syncthreads();
        if (tid < 32) {
            float s = 0.f;
#pragma unroll
            for (int ww = 0; ww < 8; ww++) s += colbuf[ww * 32 + tid];
            g_cp[(g * NATOMS + jh * 32 + tid) * 2 + ih] = s;
        }

        /* last of 4 consumers resets counters (all have passed the spin) */
        __threadfence();
        __syncthreads();
        if (tid == 0) {
            int old = atomicAdd(&g_done[g], 1);
            if (old == 3) {
                atomicExch(&g_cnt[g], 0);
                atomicExch(&g_done[g], 0);
            }
        }
    }
}

/* ---------------- normalize ---------------- */
__global__ void __launch_bounds__(64) finalize_kernel(float* __restrict__ out)
{
    int b = blockIdx.x, i = threadIdx.x;
    float r = g_rp[(b * 64 + i) * 2] + g_rp[(b * 64 + i) * 2 + 1];
    float c = g_cp[(b * 64 + i) * 2] + g_cp[(b * 64 + i) * 2 + 1];
    __shared__ float red[64];
    red[i] = r;
    __syncthreads();
    if (i < 32) {
        float v = red[i] + red[i + 32];
#pragma unroll
        for (int o = 16; o > 0; o >>= 1)
            v += __shfl_xor_sync(0xffffffffu, v, o);
        if (i == 0) red[0] = v;
    }
    __syncthreads();
    float inv = 1.f / red[0];
    out[b * 64 + i] = r * inv;
    out[BATCH * NATOMS + b * 64 + i] = c * inv;
}

extern "C" void kernel_launch(void* const* d_in, const int* in_sizes, int n_in,
                              void* d_out, int out_size)
{
    const float *h1 = nullptr, *h2 = nullptr, *W1 = nullptr,
                *b1 = nullptr, *W2 = nullptr;
    for (int idx = 0; idx < n_in; idx++) {
        int sz = in_sizes[idx];
        if (sz == BATCH * NATOMS * HDIM) {
            if (!h1) h1 = (const float*)d_in[idx];
            else if (!h2) h2 = (const float*)d_in[idx];
        } else if (sz == 2 * HDIM * HDIM) {
            W1 = (const float*)d_in[idx];
        } else if (sz == HDIM) {
            if (!b1) b1 = (const float*)d_in[idx];
            else if (!W2) W2 = (const float*)d_in[idx];
        }
    }
    float* out = (float*)d_out;

    merged_kernel<<<768, 256, SMEM_BYTES>>>(h1, h2, W1, b1, W2);
    finalize_kernel<<<BATCH, 64>>>(out);
}

// round 15
// speedup vs baseline: 1.2543x; 1.2168x over previous
#include <cuda_runtime.h>
#include <cuda_fp16.h>

#define BATCH   64
#define NATOMS  64
#define HDIM    256
#define NROWS   (2 * BATCH * NATOMS)   /* 8192 */
#define H2      (HDIM / 2)             /* 128 half2 per row */

/* s = [h1@W1[:H]+b1 ; h2@W1[H:]] packed half2 (4 MB) */
__device__ unsigned g_sh[NROWS * H2];
__device__ float g_rp[BATCH * NATOMS * 2];   /* row partials, 2 jh-halves */
__device__ float g_cp[BATCH * NATOMS * 2];   /* col partials, 2 ih-halves */

__device__ __forceinline__ unsigned pack_h2(float x, float y) {
    __half2 h = __floats2half2_rn(x, y);
    return *reinterpret_cast<unsigned*>(&h);
}
__device__ __forceinline__ unsigned tanh2u(unsigned x) {
    unsigned y; asm("tanh.approx.f16x2 %0, %1;" : "=r"(y) : "r"(x)); return y;
}
__device__ __forceinline__ __half2 u2h(unsigned u) {
    return *reinterpret_cast<__half2*>(&u);
}
__device__ __forceinline__ unsigned hadd2u(unsigned a, unsigned b) {
    __half2 r = __hadd2(u2h(a), u2h(b));
    return *reinterpret_cast<unsigned*>(&r);
}
__device__ __forceinline__ void cp_async16(void* smem, const void* gmem) {
    unsigned s = (unsigned)__cvta_generic_to_shared(smem);
    asm volatile("cp.async.cg.shared.global [%0], [%1], 16;" :: "r"(s), "l"(gmem));
}

/* ===== tf32 tensor GEMM: R6/R10-proven (64x64, 128 thr, 2-stage) ===== */
__global__ void __launch_bounds__(128) gemm_kernel(
    const float* __restrict__ h1, const float* __restrict__ h2,
    const float* __restrict__ W1, const float* __restrict__ b1)
{
    __shared__ float As[2][64 * 36];   /* [row][k], pad 36 -> conflict-free */
    __shared__ float Bs[2][32 * 72];   /* [k][n],   pad 72 -> conflict-free */

    const int row0 = blockIdx.x * 64;
    const int n0   = blockIdx.y * 64;
    const bool second = (row0 >= BATCH * NATOMS);
    const float* A = second ? h2 + (row0 - BATCH * NATOMS) * HDIM
                            : h1 + row0 * HDIM;
    const float* W = W1 + (second ? HDIM * HDIM : 0);

    const int tid = threadIdx.x;
    const int lane = tid & 31, w = tid >> 5;
    const int wm = w >> 1, wn = w & 1;
    const int gid = lane >> 2, tig = lane & 3;

    int ar[4], ac[4], bk[4], bn[4];
#pragma unroll
    for (int l = 0; l < 4; l++) {
        int f = tid + l * 128;
        ar[l] = f >> 3;  ac[l] = f & 7;
        bk[l] = f >> 4;  bn[l] = f & 15;
    }

    float acc[2][4][4];
#pragma unroll
    for (int mt = 0; mt < 2; mt++)
#pragma unroll
        for (int nt = 0; nt < 4; nt++)
#pragma unroll
            for (int q = 0; q < 4; q++) acc[mt][nt][q] = 0.f;

#pragma unroll
    for (int l = 0; l < 4; l++)
        cp_async16(&As[0][ar[l] * 36 + ac[l] * 4], A + ar[l] * HDIM + ac[l] * 4);
#pragma unroll
    for (int l = 0; l < 4; l++)
        cp_async16(&Bs[0][bk[l] * 72 + bn[l] * 4], W + bk[l] * HDIM + n0 + bn[l] * 4);
    asm volatile("cp.async.commit_group;");

    for (int kci = 0; kci < 8; kci++) {
        const int s = kci & 1;
        if (kci + 1 < 8) {
            const int kc = (kci + 1) * 32;
#pragma unroll
            for (int l = 0; l < 4; l++)
                cp_async16(&As[s ^ 1][ar[l] * 36 + ac[l] * 4],
                           A + ar[l] * HDIM + kc + ac[l] * 4);
#pragma unroll
            for (int l = 0; l < 4; l++)
                cp_async16(&Bs[s ^ 1][bk[l] * 72 + bn[l] * 4],
                           W + (kc + bk[l]) * HDIM + n0 + bn[l] * 4);
            asm volatile("cp.async.commit_group;");
            asm volatile("cp.async.wait_group 1;");
        } else {
            asm volatile("cp.async.wait_group 0;");
        }
        __syncthreads();

        const unsigned* Au = (const unsigned*)As[s];
        const unsigned* Bu = (const unsigned*)Bs[s];
#pragma unroll
        for (int ks = 0; ks < 4; ks++) {
            unsigned a[2][4], bfr[4][2];
#pragma unroll
            for (int mt = 0; mt < 2; mt++) {
                int r = wm * 32 + mt * 16 + gid;
                int kk = ks * 8 + tig;
                a[mt][0] = Au[r * 36 + kk];
                a[mt][1] = Au[(r + 8) * 36 + kk];
                a[mt][2] = Au[r * 36 + kk + 4];
                a[mt][3] = Au[(r + 8) * 36 + kk + 4];
            }
#pragma unroll
            for (int nt = 0; nt < 4; nt++) {
                int c = wn * 32 + nt * 8 + gid;
                bfr[nt][0] = Bu[(ks * 8 + tig) * 72 + c];
                bfr[nt][1] = Bu[(ks * 8 + tig + 4) * 72 + c];
            }
#pragma unroll
            for (int mt = 0; mt < 2; mt++)
#pragma unroll
                for (int nt = 0; nt < 4; nt++)
                    asm volatile(
                        "mma.sync.aligned.m16n8k8.row.col.f32.tf32.tf32.f32 "
                        "{%0,%1,%2,%3}, {%4,%5,%6,%7}, {%8,%9}, {%0,%1,%2,%3};"
                        : "+f"(acc[mt][nt][0]), "+f"(acc[mt][nt][1]),
                          "+f"(acc[mt][nt][2]), "+f"(acc[mt][nt][3])
                        : "r"(a[mt][0]), "r"(a[mt][1]), "r"(a[mt][2]), "r"(a[mt][3]),
                          "r"(bfr[nt][0]), "r"(bfr[nt][1]));
        }
        __syncthreads();
    }

#pragma unroll
    for (int mt = 0; mt < 2; mt++) {
        int r = row0 + wm * 32 + mt * 16 + gid;
#pragma unroll
        for (int nt = 0; nt < 4; nt++) {
            int col = n0 + wn * 32 + nt * 8 + tig * 2;
            float bx = 0.f, by = 0.f;
            if (!second) { float2 bv = *(const float2*)(b1 + col); bx = bv.x; by = bv.y; }
            g_sh[r * H2 + (col >> 1)]       = pack_h2(acc[mt][nt][0] + bx, acc[mt][nt][1] + by);
            g_sh[(r + 8) * H2 + (col >> 1)] = pack_h2(acc[mt][nt][2] + bx, acc[mt][nt][3] + by);
        }
    }
}

/* ===== score: 256 CTAs x 512 thr (16 warps), 32i x 32j, 2 i-rows/warp ===== */
__global__ void __launch_bounds__(512) score_kernel(const float* __restrict__ W2)
{
    __shared__ unsigned s1s[32 * 128];   /* [i][hh] half2, 16 KB           */
    __shared__ unsigned s2s[32 * 129];   /* [j][hh] pad 129: conflict-free */
    __shared__ float2   w2s[128];
    __shared__ float    colbuf[16][32];

    const int jh = blockIdx.x, ih = blockIdx.y, b = blockIdx.z;
    const int tid = threadIdx.x, lane = tid & 31, w = tid >> 5;

    if (tid < 128) w2s[tid] = *(const float2*)(W2 + tid * 2);

    /* s1: 32 rows x 128 half2 = 1024 uint4 (2/thread), linear */
    const unsigned* s1g = g_sh + (size_t)(b * NATOMS + ih * 32) * H2;
#pragma unroll
    for (int l = 0; l < 2; l++) {
        int f = tid + l * 512;
        *(uint4*)&s1s[f * 4] = *(const uint4*)(s1g + f * 4);
    }
    /* s2: 32 rows, pad-129 scalar stores (2 uint4/thread) — proven pattern */
    const unsigned* s2g = g_sh + (size_t)(BATCH * NATOMS + b * NATOMS + jh * 32) * H2;
#pragma unroll
    for (int l = 0; l < 2; l++) {
        int f = tid + l * 512;
        int j = f >> 5, q = f & 31;
        uint4 v = *(const uint4*)(s2g + f * 4);
        unsigned* d = &s2s[j * 129 + q * 4];
        d[0] = v.x; d[1] = v.y; d[2] = v.z; d[3] = v.w;
    }
    __syncthreads();

    /* warp w owns i rows [2w, 2w+2), lane = local j — proven inner loop */
    const unsigned* s2row = &s2s[lane * 129];
    float accA[2], accB[2];
    accA[0] = accA[1] = accB[0] = accB[1] = 0.f;

#pragma unroll 4
    for (int hh = 0; hh < 128; hh++) {
        float2 wv = w2s[hh];           /* broadcast */
        unsigned b2 = s2row[hh];       /* conflict-free */
#pragma unroll
        for (int ii = 0; ii < 2; ii++) {
            unsigned a2 = s1s[(w * 2 + ii) * 128 + hh];   /* broadcast */
            unsigned th = tanh2u(hadd2u(a2, b2));
            float2 tf = __half22float2(u2h(th));
            accA[ii] = fmaf(wv.x, tf.x, accA[ii]);
            accB[ii] = fmaf(wv.y, tf.y, accB[ii]);
        }
    }

    float colacc = 0.f;
#pragma unroll
    for (int ii = 0; ii < 2; ii++) {
        float e = __expf(accA[ii] + accB[ii]);   /* bounded: no max pass */
        colacc += e;
        float rs = e;
#pragma unroll
        for (int o = 16; o > 0; o >>= 1)
            rs += __shfl_xor_sync(0xffffffffu, rs, o);
        if (lane == 0)
            g_rp[(b * NATOMS + ih * 32 + w * 2 + ii) * 2 + jh] = rs;
    }
    colbuf[w][lane] = colacc;
    __syncthreads();
    if (tid < 32) {
        float s = 0.f;
#pragma unroll
        for (int ww = 0; ww < 16; ww++) s += colbuf[ww][tid];
        g_cp[(b * NATOMS + jh * 32 + tid) * 2 + ih] = s;
    }
}

/* ---------------- normalize (R7-proven) ---------------- */
__global__ void __launch_bounds__(64) finalize_kernel(float* __restrict__ out)
{
    int b = blockIdx.x, i = threadIdx.x;
    float r = g_rp[(b * 64 + i) * 2] + g_rp[(b * 64 + i) * 2 + 1];
    float c = g_cp[(b * 64 + i) * 2] + g_cp[(b * 64 + i) * 2 + 1];
    __shared__ float red[64];
    red[i] = r;
    __syncthreads();
    if (i < 32) {
        float v = red[i] + red[i + 32];
#pragma unroll
        for (int o = 16; o > 0; o >>= 1)
            v += __shfl_xor_sync(0xffffffffu, v, o);
        if (i == 0) red[0] = v;
    }
    __syncthreads();
    float inv = 1.f / red[0];
    out[b * 64 + i] = r * inv;
    out[BATCH * NATOMS + b * 64 + i] = c * inv;
}

extern "C" void kernel_launch(void* const* d_in, const int* in_sizes, int n_in,
                              void* d_out, int out_size)
{
    const float *h1 = nullptr, *h2 = nullptr, *W1 = nullptr,
                *b1 = nullptr, *W2 = nullptr;
    for (int idx = 0; idx < n_in; idx++) {
        int sz = in_sizes[idx];
        if (sz == BATCH * NATOMS * HDIM) {
            if (!h1) h1 = (const float*)d_in[idx];
            else if (!h2) h2 = (const float*)d_in[idx];
        } else if (sz == 2 * HDIM * HDIM) {
            W1 = (const float*)d_in[idx];
        } else if (sz == HDIM) {
            if (!b1) b1 = (const float*)d_in[idx];
            else if (!W2) W2 = (const float*)d_in[idx];
        }
    }
    float* out = (float*)d_out;

    gemm_kernel<<<dim3(NROWS / 64, HDIM / 64), 128>>>(h1, h2, W1, b1);
    score_kernel<<<dim3(2, 2, BATCH), 512>>>(W2);
    finalize_kernel<<<BATCH, 64>>>(out);
}

// round 16
// speedup vs baseline: 1.2553x; 1.0009x over previous
#include <cuda_runtime.h>
#include <cuda_fp16.h>

#define BATCH   64
#define NATOMS  64
#define HDIM    256
#define NROWS   (2 * BATCH * NATOMS)   /* 8192 */
#define H2      (HDIM / 2)             /* 128 half2 per row */

/* s = [h1@W1[:H]+b1 ; h2@W1[H:]] packed half2 (4 MB) */
__device__ unsigned g_sh[NROWS * H2];
__device__ float g_rp[BATCH * NATOMS * 2];   /* row partials, 2 jh-halves */
__device__ float g_cp[BATCH * NATOMS * 2];   /* col partials, 2 ih-halves */

__device__ __forceinline__ unsigned pack_h2(float x, float y) {
    __half2 h = __floats2half2_rn(x, y);
    return *reinterpret_cast<unsigned*>(&h);
}
__device__ __forceinline__ float tanhf32(float x) {
    float y; asm("tanh.approx.f32 %0, %1;" : "=f"(y) : "f"(x)); return y;
}
__device__ __forceinline__ __half2 u2h(unsigned u) {
    return *reinterpret_cast<__half2*>(&u);
}
__device__ __forceinline__ unsigned hadd2u(unsigned a, unsigned b) {
    __half2 r = __hadd2(u2h(a), u2h(b));
    return *reinterpret_cast<unsigned*>(&r);
}
__device__ __forceinline__ void cp_async16(void* smem, const void* gmem) {
    unsigned s = (unsigned)__cvta_generic_to_shared(smem);
    asm volatile("cp.async.cg.shared.global [%0], [%1], 16;" :: "r"(s), "l"(gmem));
}

/* ===== tf32 tensor GEMM: R6/R10-proven (64x64, 128 thr, 2-stage) ===== */
__global__ void __launch_bounds__(128) gemm_kernel(
    const float* __restrict__ h1, const float* __restrict__ h2,
    const float* __restrict__ W1, const float* __restrict__ b1)
{
    __shared__ float As[2][64 * 36];   /* [row][k], pad 36 -> conflict-free */
    __shared__ float Bs[2][32 * 72];   /* [k][n],   pad 72 -> conflict-free */

    const int row0 = blockIdx.x * 64;
    const int n0   = blockIdx.y * 64;
    const bool second = (row0 >= BATCH * NATOMS);
    const float* A = second ? h2 + (row0 - BATCH * NATOMS) * HDIM
                            : h1 + row0 * HDIM;
    const float* W = W1 + (second ? HDIM * HDIM : 0);

    const int tid = threadIdx.x;
    const int lane = tid & 31, w = tid >> 5;
    const int wm = w >> 1, wn = w & 1;
    const int gid = lane >> 2, tig = lane & 3;

    int ar[4], ac[4], bk[4], bn[4];
#pragma unroll
    for (int l = 0; l < 4; l++) {
        int f = tid + l * 128;
        ar[l] = f >> 3;  ac[l] = f & 7;
        bk[l] = f >> 4;  bn[l] = f & 15;
    }

    float acc[2][4][4];
#pragma unroll
    for (int mt = 0; mt < 2; mt++)
#pragma unroll
        for (int nt = 0; nt < 4; nt++)
#pragma unroll
            for (int q = 0; q < 4; q++) acc[mt][nt][q] = 0.f;

#pragma unroll
    for (int l = 0; l < 4; l++)
        cp_async16(&As[0][ar[l] * 36 + ac[l] * 4], A + ar[l] * HDIM + ac[l] * 4);
#pragma unroll
    for (int l = 0; l < 4; l++)
        cp_async16(&Bs[0][bk[l] * 72 + bn[l] * 4], W + bk[l] * HDIM + n0 + bn[l] * 4);
    asm volatile("cp.async.commit_group;");

    for (int kci = 0; kci < 8; kci++) {
        const int s = kci & 1;
        if (kci + 1 < 8) {
            const int kc = (kci + 1) * 32;
#pragma unroll
            for (int l = 0; l < 4; l++)
                cp_async16(&As[s ^ 1][ar[l] * 36 + ac[l] * 4],
                           A + ar[l] * HDIM + kc + ac[l] * 4);
#pragma unroll
            for (int l = 0; l < 4; l++)
                cp_async16(&Bs[s ^ 1][bk[l] * 72 + bn[l] * 4],
                           W + (kc + bk[l]) * HDIM + n0 + bn[l] * 4);
            asm volatile("cp.async.commit_group;");
            asm volatile("cp.async.wait_group 1;");
        } else {
            asm volatile("cp.async.wait_group 0;");
        }
        __syncthreads();

        const unsigned* Au = (const unsigned*)As[s];
        const unsigned* Bu = (const unsigned*)Bs[s];
#pragma unroll
        for (int ks = 0; ks < 4; ks++) {
            unsigned a[2][4], bfr[4][2];
#pragma unroll
            for (int mt = 0; mt < 2; mt++) {
                int r = wm * 32 + mt * 16 + gid;
                int kk = ks * 8 + tig;
                a[mt][0] = Au[r * 36 + kk];
                a[mt][1] = Au[(r + 8) * 36 + kk];
                a[mt][2] = Au[r * 36 + kk + 4];
                a[mt][3] = Au[(r + 8) * 36 + kk + 4];
            }
#pragma unroll
            for (int nt = 0; nt < 4; nt++) {
                int c = wn * 32 + nt * 8 + gid;
                bfr[nt][0] = Bu[(ks * 8 + tig) * 72 + c];
                bfr[nt][1] = Bu[(ks * 8 + tig + 4) * 72 + c];
            }
#pragma unroll
            for (int mt = 0; mt < 2; mt++)
#pragma unroll
                for (int nt = 0; nt < 4; nt++)
                    asm volatile(
                        "mma.sync.aligned.m16n8k8.row.col.f32.tf32.tf32.f32 "
                        "{%0,%1,%2,%3}, {%4,%5,%6,%7}, {%8,%9}, {%0,%1,%2,%3};"
                        : "+f"(acc[mt][nt][0]), "+f"(acc[mt][nt][1]),
                          "+f"(acc[mt][nt][2]), "+f"(acc[mt][nt][3])
                        : "r"(a[mt][0]), "r"(a[mt][1]), "r"(a[mt][2]), "r"(a[mt][3]),
                          "r"(bfr[nt][0]), "r"(bfr[nt][1]));
        }
        __syncthreads();
    }

#pragma unroll
    for (int mt = 0; mt < 2; mt++) {
        int r = row0 + wm * 32 + mt * 16 + gid;
#pragma unroll
        for (int nt = 0; nt < 4; nt++) {
            int col = n0 + wn * 32 + nt * 8 + tig * 2;
            float bx = 0.f, by = 0.f;
            if (!second) { float2 bv = *(const float2*)(b1 + col); bx = bv.x; by = bv.y; }
            g_sh[r * H2 + (col >> 1)]       = pack_h2(acc[mt][nt][0] + bx, acc[mt][nt][1] + by);
            g_sh[(r + 8) * H2 + (col >> 1)] = pack_h2(acc[mt][nt][2] + bx, acc[mt][nt][3] + by);
        }
    }
}

/* ===== score: proven structure, tanh moved to f32 MUFU (rt 8) ===== */
__global__ void __launch_bounds__(512) score_kernel(const float* __restrict__ W2)
{
    __shared__ unsigned s1s[32 * 128];   /* [i][hh] half2, 16 KB           */
    __shared__ unsigned s2s[32 * 129];   /* [j][hh] pad 129: conflict-free */
    __shared__ float2   w2s[128];
    __shared__ float    colbuf[16][32];

    const int jh = blockIdx.x, ih = blockIdx.y, b = blockIdx.z;
    const int tid = threadIdx.x, lane = tid & 31, w = tid >> 5;

    if (tid < 128) w2s[tid] = *(const float2*)(W2 + tid * 2);

    /* s1: 32 rows x 128 half2 = 1024 uint4 (2/thread), linear */
    const unsigned* s1g = g_sh + (size_t)(b * NATOMS + ih * 32) * H2;
#pragma unroll
    for (int l = 0; l < 2; l++) {
        int f = tid + l * 512;
        *(uint4*)&s1s[f * 4] = *(const uint4*)(s1g + f * 4);
    }
    /* s2: 32 rows, pad-129 scalar stores (2 uint4/thread) — proven pattern */
    const unsigned* s2g = g_sh + (size_t)(BATCH * NATOMS + b * NATOMS + jh * 32) * H2;
#pragma unroll
    for (int l = 0; l < 2; l++) {
        int f = tid + l * 512;
        int j = f >> 5, q = f & 31;
        uint4 v = *(const uint4*)(s2g + f * 4);
        unsigned* d = &s2s[j * 129 + q * 4];
        d[0] = v.x; d[1] = v.y; d[2] = v.z; d[3] = v.w;
    }
    __syncthreads();

    /* warp w owns i rows [2w, 2w+2), lane = local j */
    const unsigned* s2row = &s2s[lane * 129];
    float accA[2], accB[2];
    accA[0] = accA[1] = accB[0] = accB[1] = 0.f;

#pragma unroll 4
    for (int hh = 0; hh < 128; hh++) {
        float2 wv = w2s[hh];           /* broadcast */
        unsigned b2 = s2row[hh];       /* conflict-free */
#pragma unroll
        for (int ii = 0; ii < 2; ii++) {
            unsigned a2 = s1s[(w * 2 + ii) * 128 + hh];   /* broadcast */
            float2 xf = __half22float2(u2h(hadd2u(a2, b2)));
            float t0 = tanhf32(xf.x);            /* MUFU f32, rt 8 */
            float t1 = tanhf32(xf.y);
            accA[ii] = fmaf(wv.x, t0, accA[ii]);
            accB[ii] = fmaf(wv.y, t1, accB[ii]);
        }
    }

    float colacc = 0.f;
#pragma unroll
    for (int ii = 0; ii < 2; ii++) {
        float e = __expf(accA[ii] + accB[ii]);   /* bounded: no max pass */
        colacc += e;
        float rs = e;
#pragma unroll
        for (int o = 16; o > 0; o >>= 1)
            rs += __shfl_xor_sync(0xffffffffu, rs, o);
        if (lane == 0)
            g_rp[(b * NATOMS + ih * 32 + w * 2 + ii) * 2 + jh] = rs;
    }
    colbuf[w][lane] = colacc;
    __syncthreads();
    if (tid < 32) {
        float s = 0.f;
#pragma unroll
        for (int ww = 0; ww < 16; ww++) s += colbuf[ww][tid];
        g_cp[(b * NATOMS + jh * 32 + tid) * 2 + ih] = s;
    }
}

/* ---------------- normalize (R7-proven) ---------------- */
__global__ void __launch_bounds__(64) finalize_kernel(float* __restrict__ out)
{
    int b = blockIdx.x, i = threadIdx.x;
    float r = g_rp[(b * 64 + i) * 2] + g_rp[(b * 64 + i) * 2 + 1];
    float c = g_cp[(b * 64 + i) * 2] + g_cp[(b * 64 + i) * 2 + 1];
    __shared__ float red[64];
    red[i] = r;
    __syncthreads();
    if (i < 32) {
        float v = red[i] + red[i + 32];
#pragma unroll
        for (int o = 16; o > 0; o >>= 1)
            v += __shfl_xor_sync(0xffffffffu, v, o);
        if (i == 0) red[0] = v;
    }
    __syncthreads();
    float inv = 1.f / red[0];
    out[b * 64 + i] = r * inv;
    out[BATCH * NATOMS + b * 64 + i] = c * inv;
}

extern "C" void kernel_launch(void* const* d_in, const int* in_sizes, int n_in,
                              void* d_out, int out_size)
{
    const float *h1 = nullptr, *h2 = nullptr, *W1 = nullptr,
                *b1 = nullptr, *W2 = nullptr;
    for (int idx = 0; idx < n_in; idx++) {
        int sz = in_sizes[idx];
        if (sz == BATCH * NATOMS * HDIM) {
            if (!h1) h1 = (const float*)d_in[idx];
            else if (!h2) h2 = (const float*)d_in[idx];
        } else if (sz == 2 * HDIM * HDIM) {
            W1 = (const float*)d_in[idx];
        } else if (sz == HDIM) {
            if (!b1) b1 = (const float*)d_in[idx];
            else if (!W2) W2 = (const float*)d_in[idx];
        }
    }
    float* out = (float*)d_out;

    gemm_kernel<<<dim3(NROWS / 64, HDIM / 64), 128>>>(h1, h2, W1, b1);
    score_kernel<<<dim3(2, 2, BATCH), 512>>>(W2);
    finalize_kernel<<<BATCH, 64>>>(out);
}

// round 17
// speedup vs baseline: 1.2650x; 1.0077x over previous
#include <cuda_runtime.h>
#include <cuda_fp16.h>

#define BATCH   64
#define NATOMS  64
#define HDIM    256
#define NROWS   (2 * BATCH * NATOMS)   /* 8192 */
#define H2      (HDIM / 2)             /* 128 half2 per row */

/* s = [h1@W1[:H]+b1 ; h2@W1[H:]] packed half2 (4 MB) */
__device__ unsigned g_sh[NROWS * H2];
__device__ float g_rp[BATCH * NATOMS * 2];   /* row partials, 2 jh-halves */
__device__ float g_cp[BATCH * NATOMS * 2];   /* col partials, 2 ih-halves */

__device__ __forceinline__ unsigned pack_h2(float x, float y) {
    __half2 h = __floats2half2_rn(x, y);
    return *reinterpret_cast<unsigned*>(&h);
}
__device__ __forceinline__ float tanhf32(float x) {
    float y; asm("tanh.approx.f32 %0, %1;" : "=f"(y) : "f"(x)); return y;
}
__device__ __forceinline__ __half2 u2h(unsigned u) {
    return *reinterpret_cast<__half2*>(&u);
}
__device__ __forceinline__ unsigned hadd2u(unsigned a, unsigned b) {
    __half2 r = __hadd2(u2h(a), u2h(b));
    return *reinterpret_cast<unsigned*>(&r);
}
__device__ __forceinline__ void cp_async16(void* smem, const void* gmem) {
    unsigned s = (unsigned)__cvta_generic_to_shared(smem);
    asm volatile("cp.async.cg.shared.global [%0], [%1], 16;" :: "r"(s), "l"(gmem));
}

/* ===== tf32 tensor GEMM: R6/R10-proven (64x64, 128 thr, 2-stage) ===== */
__global__ void __launch_bounds__(128) gemm_kernel(
    const float* __restrict__ h1, const float* __restrict__ h2,
    const float* __restrict__ W1, const float* __restrict__ b1)
{
    __shared__ float As[2][64 * 36];   /* [row][k], pad 36 -> conflict-free */
    __shared__ float Bs[2][32 * 72];   /* [k][n],   pad 72 -> conflict-free */

    const int row0 = blockIdx.x * 64;
    const int n0   = blockIdx.y * 64;
    const bool second = (row0 >= BATCH * NATOMS);
    const float* A = second ? h2 + (row0 - BATCH * NATOMS) * HDIM
                            : h1 + row0 * HDIM;
    const float* W = W1 + (second ? HDIM * HDIM : 0);

    const int tid = threadIdx.x;
    const int lane = tid & 31, w = tid >> 5;
    const int wm = w >> 1, wn = w & 1;
    const int gid = lane >> 2, tig = lane & 3;

    int ar[4], ac[4], bk[4], bn[4];
#pragma unroll
    for (int l = 0; l < 4; l++) {
        int f = tid + l * 128;
        ar[l] = f >> 3;  ac[l] = f & 7;
        bk[l] = f >> 4;  bn[l] = f & 15;
    }

    float acc[2][4][4];
#pragma unroll
    for (int mt = 0; mt < 2; mt++)
#pragma unroll
        for (int nt = 0; nt < 4; nt++)
#pragma unroll
            for (int q = 0; q < 4; q++) acc[mt][nt][q] = 0.f;

#pragma unroll
    for (int l = 0; l < 4; l++)
        cp_async16(&As[0][ar[l] * 36 + ac[l] * 4], A + ar[l] * HDIM + ac[l] * 4);
#pragma unroll
    for (int l = 0; l < 4; l++)
        cp_async16(&Bs[0][bk[l] * 72 + bn[l] * 4], W + bk[l] * HDIM + n0 + bn[l] * 4);
    asm volatile("cp.async.commit_group;");

    for (int kci = 0; kci < 8; kci++) {
        const int s = kci & 1;
        if (kci + 1 < 8) {
            const int kc = (kci + 1) * 32;
#pragma unroll
            for (int l = 0; l < 4; l++)
                cp_async16(&As[s ^ 1][ar[l] * 36 + ac[l] * 4],
                           A + ar[l] * HDIM + kc + ac[l] * 4);
#pragma unroll
            for (int l = 0; l < 4; l++)
                cp_async16(&Bs[s ^ 1][bk[l] * 72 + bn[l] * 4],
                           W + (kc + bk[l]) * HDIM + n0 + bn[l] * 4);
            asm volatile("cp.async.commit_group;");
            asm volatile("cp.async.wait_group 1;");
        } else {
            asm volatile("cp.async.wait_group 0;");
        }
        __syncthreads();

        const unsigned* Au = (const unsigned*)As[s];
        const unsigned* Bu = (const unsigned*)Bs[s];
#pragma unroll
        for (int ks = 0; ks < 4; ks++) {
            unsigned a[2][4], bfr[4][2];
#pragma unroll
            for (int mt = 0; mt < 2; mt++) {
                int r = wm * 32 + mt * 16 + gid;
                int kk = ks * 8 + tig;
                a[mt][0] = Au[r * 36 + kk];
                a[mt][1] = Au[(r + 8) * 36 + kk];
                a[mt][2] = Au[r * 36 + kk + 4];
                a[mt][3] = Au[(r + 8) * 36 + kk + 4];
            }
#pragma unroll
            for (int nt = 0; nt < 4; nt++) {
                int c = wn * 32 + nt * 8 + gid;
                bfr[nt][0] = Bu[(ks * 8 + tig) * 72 + c];
                bfr[nt][1] = Bu[(ks * 8 + tig + 4) * 72 + c];
            }
#pragma unroll
            for (int mt = 0; mt < 2; mt++)
#pragma unroll
                for (int nt = 0; nt < 4; nt++)
                    asm volatile(
                        "mma.sync.aligned.m16n8k8.row.col.f32.tf32.tf32.f32 "
                        "{%0,%1,%2,%3}, {%4,%5,%6,%7}, {%8,%9}, {%0,%1,%2,%3};"
                        : "+f"(acc[mt][nt][0]), "+f"(acc[mt][nt][1]),
                          "+f"(acc[mt][nt][2]), "+f"(acc[mt][nt][3])
                        : "r"(a[mt][0]), "r"(a[mt][1]), "r"(a[mt][2]), "r"(a[mt][3]),
                          "r"(bfr[nt][0]), "r"(bfr[nt][1]));
        }
        __syncthreads();
    }

#pragma unroll
    for (int mt = 0; mt < 2; mt++) {
        int r = row0 + wm * 32 + mt * 16 + gid;
#pragma unroll
        for (int nt = 0; nt < 4; nt++) {
            int col = n0 + wn * 32 + nt * 8 + tig * 2;
            float bx = 0.f, by = 0.f;
            if (!second) { float2 bv = *(const float2*)(b1 + col); bx = bv.x; by = bv.y; }
            g_sh[r * H2 + (col >> 1)]       = pack_h2(acc[mt][nt][0] + bx, acc[mt][nt][1] + by);
            g_sh[(r + 8) * H2 + (col >> 1)] = pack_h2(acc[mt][nt][2] + bx, acc[mt][nt][3] + by);
        }
    }
}

/* ===== score: R16 arithmetic, LDS wavefronts halved (2 hh per iter) ===== */
__global__ void __launch_bounds__(512) score_kernel(const float* __restrict__ W2)
{
    __shared__ unsigned s1s[32 * 128];   /* [i][hh] half2                    */
    __shared__ unsigned s2s[32 * 130];   /* [j][hh] pad 130: LDS.64-safe     */
    __shared__ float4   w2s4[64];        /* w2 as float4 (2 hh per entry)    */
    __shared__ float    colbuf[16][32];

    const int jh = blockIdx.x, ih = blockIdx.y, b = blockIdx.z;
    const int tid = threadIdx.x, lane = tid & 31, w = tid >> 5;

    if (tid < 64) w2s4[tid] = *(const float4*)(W2 + tid * 4);

    /* s1: 32 rows x 128 half2 = 1024 uint4 (2/thread), linear */
    const unsigned* s1g = g_sh + (size_t)(b * NATOMS + ih * 32) * H2;
#pragma unroll
    for (int l = 0; l < 2; l++) {
        int f = tid + l * 512;
        *(uint4*)&s1s[f * 4] = *(const uint4*)(s1g + f * 4);
    }
    /* s2: 32 rows, pad-130 rows (2 uint4/thread, scalar stores) */
    const unsigned* s2g = g_sh + (size_t)(BATCH * NATOMS + b * NATOMS + jh * 32) * H2;
#pragma unroll
    for (int l = 0; l < 2; l++) {
        int f = tid + l * 512;
        int j = f >> 5, q = f & 31;
        uint4 v = *(const uint4*)(s2g + f * 4);
        unsigned* d = &s2s[j * 130 + q * 4];
        d[0] = v.x; d[1] = v.y; d[2] = v.z; d[3] = v.w;
    }
    __syncthreads();

    /* warp w owns i rows [2w, 2w+2), lane = local j; 2 hh per iteration */
    const unsigned* s2row = &s2s[lane * 130];
    float accA[2], accB[2];
    accA[0] = accA[1] = accB[0] = accB[1] = 0.f;

#pragma unroll 4
    for (int hp = 0; hp < 64; hp++) {
        float4 wv = w2s4[hp];                        /* LDS.128 broadcast     */
        uint2 b2 = *(const uint2*)&s2row[hp * 2];    /* LDS.64 conflict-free  */
#pragma unroll
        for (int ii = 0; ii < 2; ii++) {
            uint2 a2 = *(const uint2*)&s1s[(w * 2 + ii) * 128 + hp * 2]; /* bcast */
            float2 x0 = __half22float2(u2h(hadd2u(a2.x, b2.x)));
            float2 x1 = __half22float2(u2h(hadd2u(a2.y, b2.y)));
            accA[ii] = fmaf(wv.x, tanhf32(x0.x), accA[ii]);
            accB[ii] = fmaf(wv.y, tanhf32(x0.y), accB[ii]);
            accA[ii] = fmaf(wv.z, tanhf32(x1.x), accA[ii]);
            accB[ii] = fmaf(wv.w, tanhf32(x1.y), accB[ii]);
        }
    }

    float colacc = 0.f;
#pragma unroll
    for (int ii = 0; ii < 2; ii++) {
        float e = __expf(accA[ii] + accB[ii]);   /* bounded: no max pass */
        colacc += e;
        float rs = e;
#pragma unroll
        for (int o = 16; o > 0; o >>= 1)
            rs += __shfl_xor_sync(0xffffffffu, rs, o);
        if (lane == 0)
            g_rp[(b * NATOMS + ih * 32 + w * 2 + ii) * 2 + jh] = rs;
    }
    colbuf[w][lane] = colacc;
    __syncthreads();
    if (tid < 32) {
        float s = 0.f;
#pragma unroll
        for (int ww = 0; ww < 16; ww++) s += colbuf[ww][tid];
        g_cp[(b * NATOMS + jh * 32 + tid) * 2 + ih] = s;
    }
}

/* ---------------- normalize (R7-proven) ---------------- */
__global__ void __launch_bounds__(64) finalize_kernel(float* __restrict__ out)
{
    int b = blockIdx.x, i = threadIdx.x;
    float r = g_rp[(b * 64 + i) * 2] + g_rp[(b * 64 + i) * 2 + 1];
    float c = g_cp[(b * 64 + i) * 2] + g_cp[(b * 64 + i) * 2 + 1];
    __shared__ float red[64];
    red[i] = r;
    __syncthreads();
    if (i < 32) {
        float v = red[i] + red[i + 32];
#pragma unroll
        for (int o = 16; o > 0; o >>= 1)
            v += __shfl_xor_sync(0xffffffffu, v, o);
        if (i == 0) red[0] = v;
    }
    __syncthreads();
    float inv = 1.f / red[0];
    out[b * 64 + i] = r * inv;
    out[BATCH * NATOMS + b * 64 + i] = c * inv;
}

extern "C" void kernel_launch(void* const* d_in, const int* in_sizes, int n_in,
                              void* d_out, int out_size)
{
    const float *h1 = nullptr, *h2 = nullptr, *W1 = nullptr,
                *b1 = nullptr, *W2 = nullptr;
    for (int idx = 0; idx < n_in; idx++) {
        int sz = in_sizes[idx];
        if (sz == BATCH * NATOMS * HDIM) {
            if (!h1) h1 = (const float*)d_in[idx];
            else if (!h2) h2 = (const float*)d_in[idx];
        } else if (sz == 2 * HDIM * HDIM) {
            W1 = (const float*)d_in[idx];
        } else if (sz == HDIM) {
            if (!b1) b1 = (const float*)d_in[idx];
            else if (!W2) W2 = (const float*)d_in[idx];
        }
    }
    float* out = (float*)d_out;

    gemm_kernel<<<dim3(NROWS / 64, HDIM / 64), 128>>>(h1, h2, W1, b1);
    score_kernel<<<dim3(2, 2, BATCH), 512>>>(W2);
    finalize_kernel<<<BATCH, 64>>>(out);
}